// round 3
// baseline (speedup 1.0000x reference)
#include <cuda_runtime.h>
#include <cuda_bf16.h>
#include <cstdint>
#include <cfloat>

// Problem constants
#define NPTS 32768   // candidate points per side
#define MQ   8192    // query (shortcut) points per side
#define CF   256     // feature channels

// Grid constants
#define G     64
#define G3    (G * G * G)          // 262144 cells per side
#define HCELL 0.125f
#define INVH  8.0f
#define ORI   (-4.0f)
#define CAP   8                    // points per bin
#define OVMAX 8192                 // overflow list capacity per side

// ---------------- scratch ----------------
__device__ int    g_cnt[2 * G3];                 // per-cell counts (2 MB)
__device__ float4 g_bin[2 * G3 * CAP];           // binned points (64 MB)
__device__ int    g_ovn[2];                      // overflow counts
__device__ float4 g_ov[2][OVMAX];                // overflow points
__device__ int    g_idx2[2][MQ];                 // 2nd-NN index per query

// ---------------- helpers ----------------
__device__ __forceinline__ int cell_of(float v) {
    int c = (int)floorf((v - ORI) * INVH);
    return min(max(c, 0), G - 1);
}

struct Top2 {
    float d1, d2;
    int   i1, i2;
};

__device__ __forceinline__ void t2_ins(Top2& t, float d, int j) {
    bool a = d < t.d1;
    bool b = d < t.d2;
    t.i2 = a ? t.i1 : (b ? j : t.i2);
    t.d2 = a ? t.d1 : (b ? d : t.d2);
    t.i1 = a ? j : t.i1;
    t.d1 = a ? d : t.d1;
}

// ---------------- K0: zero counts ----------------
__global__ void zero_kernel() {
    int gid = blockIdx.x * blockDim.x + threadIdx.x;
    if (gid < 2 * G3) g_cnt[gid] = 0;
    if (gid < 2) g_ovn[gid] = 0;
}

// ---------------- K1: scatter points into bins ----------------
__global__ void scatter_kernel(const float* __restrict__ src_coords,
                               const float* __restrict__ tgt_coords) {
    int u = blockIdx.x * blockDim.x + threadIdx.x;
    if (u >= 2 * NPTS) return;
    int side = u >> 15;
    int i = u & (NPTS - 1);
    const float* c = side ? tgt_coords : src_coords;
    float x = c[3 * i], y = c[3 * i + 1], z = c[3 * i + 2];
    int cell = side * G3 + (cell_of(z) * G + cell_of(y)) * G + cell_of(x);
    float4 p = make_float4(x, y, z, __int_as_float(i));
    int slot = atomicAdd(&g_cnt[cell], 1);
    if (slot < CAP) {
        g_bin[cell * CAP + slot] = p;
    } else {
        int o = atomicAdd(&g_ovn[side], 1);
        if (o < OVMAX) g_ov[side][o] = p;
    }
}

// ---------------- K2: warp-per-query top-2 search ----------------
// Scans the (2r+1)^3 cell box around the query's cell, plus the overflow
// list; lanes stride over cells. Returns per-lane partial top-2.
__device__ __forceinline__ void scan_box(int r, int cx, int cy, int cz,
                                         int sbase, int side, int lane,
                                         float qx, float qy, float qz,
                                         Top2& t) {
    t.d1 = FLT_MAX; t.d2 = FLT_MAX; t.i1 = -1; t.i2 = -1;
    int s = 2 * r + 1;
    int s2 = s * s;
    int total = s2 * s;
    for (int c = lane; c < total; c += 32) {
        int dz = c / s2;
        int rem = c - dz * s2;
        int dy = rem / s;
        int dx = rem - dy * s;
        int x = cx + dx - r, y = cy + dy - r, z = cz + dz - r;
        if ((unsigned)x >= G || (unsigned)y >= G || (unsigned)z >= G) continue;
        int cell = sbase + (z * G + y) * G + x;
        int n = min(g_cnt[cell], CAP);
        int base = cell * CAP;
        for (int k = 0; k < n; k++) {
            float4 p = g_bin[base + k];
            float ddx = qx - p.x, ddy = qy - p.y, ddz = qz - p.z;
            float d = fmaf(ddx, ddx, fmaf(ddy, ddy, ddz * ddz));
            t2_ins(t, d, __float_as_int(p.w));
        }
    }
    // overflow points (not present in any bin -> no duplicates)
    int ovn = min(g_ovn[side], OVMAX);
    for (int o = lane; o < ovn; o += 32) {
        float4 p = g_ov[side][o];
        float ddx = qx - p.x, ddy = qy - p.y, ddz = qz - p.z;
        float d = fmaf(ddx, ddx, fmaf(ddy, ddy, ddz * ddz));
        t2_ins(t, d, __float_as_int(p.w));
    }
}

__device__ __forceinline__ Top2 warp_merge(Top2 t) {
    #pragma unroll
    for (int off = 16; off; off >>= 1) {
        float od1 = __shfl_xor_sync(0xffffffffu, t.d1, off);
        int   oi1 = __shfl_xor_sync(0xffffffffu, t.i1, off);
        float od2 = __shfl_xor_sync(0xffffffffu, t.d2, off);
        int   oi2 = __shfl_xor_sync(0xffffffffu, t.i2, off);
        t2_ins(t, od1, oi1);
        t2_ins(t, od2, oi2);
    }
    return t;
}

__global__ __launch_bounds__(256)
void search_kernel(const float* __restrict__ src_sc,
                   const float* __restrict__ tgt_sc) {
    int wid = (blockIdx.x * blockDim.x + threadIdx.x) >> 5;  // global warp id
    int lane = threadIdx.x & 31;
    if (wid >= 2 * MQ) return;
    int side = wid >> 13;
    int q = wid & (MQ - 1);
    const float* sc = side ? tgt_sc : src_sc;
    float qx = sc[3 * q], qy = sc[3 * q + 1], qz = sc[3 * q + 2];
    int cx = cell_of(qx), cy = cell_of(qy), cz = cell_of(qz);
    int sbase = side * G3;

    Top2 t;
    Top2 m;
    int r = 2;
    for (;;) {
        scan_box(r, cx, cy, cz, sbase, side, lane, qx, qy, qz, t);
        m = warp_merge(t);
        float bnd = (float)r * HCELL;
        if (bnd * bnd >= m.d2 || r >= G) break;
        r <<= 1;                      // rescan bigger box (re-inits, no dups)
        if (r > G) r = G;
    }
    if (lane == 0) g_idx2[side][q] = m.i2;
}

// ---------------- K3: gather features ----------------
__global__ void gather_kernel(const float* __restrict__ src_feat,
                              const float* __restrict__ tgt_feat,
                              float* __restrict__ out) {
    int row = blockIdx.x;                 // 0 .. 2*MQ-1
    int side = (row >= MQ) ? 1 : 0;
    int q = side ? (row - MQ) : row;
    const float* f = side ? tgt_feat : src_feat;
    int idx = g_idx2[side][q];
    const float4* srcp = (const float4*)(f + (size_t)idx * CF);
    float4* dstp = (float4*)(out + (size_t)row * CF);
    dstp[threadIdx.x] = srcp[threadIdx.x];
}

extern "C" void kernel_launch(void* const* d_in, const int* in_sizes, int n_in,
                              void* d_out, int out_size) {
    const float* src        = (const float*)d_in[0];   // [N, C]
    const float* tgt        = (const float*)d_in[1];   // [N, C]
    const float* src_coords = (const float*)d_in[2];   // [N, 3]
    const float* tgt_coords = (const float*)d_in[3];   // [N, 3]
    const float* src_sc     = (const float*)d_in[4];   // [M, 3]
    const float* tgt_sc     = (const float*)d_in[5];   // [M, 3]
    float* out = (float*)d_out;                        // [2*M, C]

    zero_kernel<<<(2 * G3 + 255) / 256, 256>>>();
    scatter_kernel<<<(2 * NPTS + 255) / 256, 256>>>(src_coords, tgt_coords);
    search_kernel<<<(2 * MQ * 32 + 255) / 256, 256>>>(src_sc, tgt_sc);
    gather_kernel<<<2 * MQ, CF / 4>>>(src, tgt, out);
}

// round 4
// speedup vs baseline: 2.7469x; 2.7469x over previous
#include <cuda_runtime.h>
#include <cuda_bf16.h>
#include <cstdint>
#include <cfloat>

// Problem constants
#define NPTS 32768   // candidate points per side
#define MQ   8192    // query (shortcut) points per side
#define CF   256     // feature channels

// Grid constants
#define G     64
#define G3    (G * G * G)          // 262144 cells per side
#define HCELL 0.125f
#define INVH  8.0f
#define ORI   (-4.0f)
#define CAP   16                   // points per bin
#define OVMAX 4096                 // overflow list capacity per side
#define RBOX  2                    // phase-1 box radius (5x5x5 = 125 cells)

// ---------------- scratch ----------------
__device__ int    g_cnt[2 * G3];                 // per-cell counts (2 MB)
__device__ float4 g_bin[2 * G3 * CAP];           // binned points (134 MB)
__device__ int    g_ovn[2];                      // overflow counts
__device__ float4 g_ov[2][OVMAX];                // overflow points
__device__ int    g_idx2[2][MQ];                 // 2nd-NN index per query
__device__ int    g_failn;                       // unresolved query count
__device__ int    g_fail[2 * MQ];                // unresolved (side<<16 | q... packed)

// ---------------- helpers ----------------
__device__ __forceinline__ int cell_of(float v) {
    int c = (int)floorf((v - ORI) * INVH);
    return min(max(c, 0), G - 1);
}

struct Top2 {
    float d1, d2;
    int   i1, i2;
};

__device__ __forceinline__ void t2_ins(Top2& t, float d, int j) {
    bool a = d < t.d1;
    bool b = d < t.d2;
    t.i2 = a ? t.i1 : (b ? j : t.i2);
    t.d2 = a ? t.d1 : (b ? d : t.d2);
    t.i1 = a ? j : t.i1;
    t.d1 = a ? d : t.d1;
}

__device__ __forceinline__ Top2 warp_merge(Top2 t) {
    #pragma unroll
    for (int off = 16; off; off >>= 1) {
        float od1 = __shfl_xor_sync(0xffffffffu, t.d1, off);
        int   oi1 = __shfl_xor_sync(0xffffffffu, t.i1, off);
        float od2 = __shfl_xor_sync(0xffffffffu, t.d2, off);
        int   oi2 = __shfl_xor_sync(0xffffffffu, t.i2, off);
        t2_ins(t, od1, oi1);
        t2_ins(t, od2, oi2);
    }
    return t;
}

// ---------------- K0: zero counts ----------------
__global__ void zero_kernel() {
    int gid = blockIdx.x * blockDim.x + threadIdx.x;
    if (gid < 2 * G3) g_cnt[gid] = 0;
    if (gid < 2) g_ovn[gid] = 0;
    if (gid == 0) g_failn = 0;
}

// ---------------- K1: scatter points into bins ----------------
__global__ void scatter_kernel(const float* __restrict__ src_coords,
                               const float* __restrict__ tgt_coords) {
    int u = blockIdx.x * blockDim.x + threadIdx.x;
    if (u >= 2 * NPTS) return;
    int side = u >> 15;
    int i = u & (NPTS - 1);
    const float* c = side ? tgt_coords : src_coords;
    float x = c[3 * i], y = c[3 * i + 1], z = c[3 * i + 2];
    int cell = side * G3 + (cell_of(z) * G + cell_of(y)) * G + cell_of(x);
    float4 p = make_float4(x, y, z, __int_as_float(i));
    int slot = atomicAdd(&g_cnt[cell], 1);
    if (slot < CAP) {
        g_bin[cell * CAP + slot] = p;
    } else {
        int o = atomicAdd(&g_ovn[side], 1);
        if (o < OVMAX) g_ov[side][o] = p;
    }
}

// ---------------- K2: phase-1 warp-per-query, fixed r=2 box ----------------
__global__ __launch_bounds__(256)
void search1_kernel(const float* __restrict__ src_sc,
                    const float* __restrict__ tgt_sc) {
    int wid = (blockIdx.x * blockDim.x + threadIdx.x) >> 5;
    int lane = threadIdx.x & 31;
    if (wid >= 2 * MQ) return;
    int side = wid >> 13;
    int q = wid & (MQ - 1);
    const float* sc = side ? tgt_sc : src_sc;
    float qx = sc[3 * q], qy = sc[3 * q + 1], qz = sc[3 * q + 2];
    int cx = cell_of(qx), cy = cell_of(qy), cz = cell_of(qz);
    int sbase = side * G3;

    Top2 t;
    t.d1 = FLT_MAX; t.d2 = FLT_MAX; t.i1 = -1; t.i2 = -1;

    const int S = 2 * RBOX + 1;            // 5
    const int TOT = S * S * S;             // 125
    for (int c = lane; c < TOT; c += 32) {
        int dz = c / (S * S);
        int rem = c - dz * (S * S);
        int dy = rem / S;
        int dx = rem - dy * S;
        int x = cx + dx - RBOX, y = cy + dy - RBOX, z = cz + dz - RBOX;
        if ((unsigned)x >= G || (unsigned)y >= G || (unsigned)z >= G) continue;
        int cell = sbase + (z * G + y) * G + x;
        int n = min(g_cnt[cell], CAP);
        int base = cell * CAP;
        for (int k = 0; k < n; k++) {
            float4 p = g_bin[base + k];
            float ddx = qx - p.x, ddy = qy - p.y, ddz = qz - p.z;
            float d = fmaf(ddx, ddx, fmaf(ddy, ddy, ddz * ddz));
            t2_ins(t, d, __float_as_int(p.w));
        }
    }
    // overflow points (never duplicated in bins)
    int ovn = min(g_ovn[side], OVMAX);
    for (int o = lane; o < ovn; o += 32) {
        float4 p = g_ov[side][o];
        float ddx = qx - p.x, ddy = qy - p.y, ddz = qz - p.z;
        float d = fmaf(ddx, ddx, fmaf(ddy, ddy, ddz * ddz));
        t2_ins(t, d, __float_as_int(p.w));
    }

    Top2 m = warp_merge(t);
    const float bnd2 = (RBOX * HCELL) * (RBOX * HCELL);   // 0.0625
    if (m.d2 <= bnd2) {
        if (lane == 0) g_idx2[side][q] = m.i2;
    } else {
        if (lane == 0) {
            int o = atomicAdd(&g_failn, 1);
            g_fail[o] = (side << 16) | q;
        }
    }
}

// ---------------- K3: phase-2 exact brute force for unresolved ----------------
__global__ __launch_bounds__(256)
void search2_kernel(const float* __restrict__ src_coords,
                    const float* __restrict__ tgt_coords,
                    const float* __restrict__ src_sc,
                    const float* __restrict__ tgt_sc) {
    int w = (blockIdx.x * blockDim.x + threadIdx.x) >> 5;
    int lane = threadIdx.x & 31;
    int nwarps = (gridDim.x * blockDim.x) >> 5;
    int nf = g_failn;

    for (int item = w; item < nf; item += nwarps) {
        int packed = g_fail[item];
        int side = packed >> 16;
        int q = packed & 0xffff;
        const float* sc = side ? tgt_sc : src_sc;
        const float* c  = side ? tgt_coords : src_coords;
        float qx = sc[3 * q], qy = sc[3 * q + 1], qz = sc[3 * q + 2];

        Top2 t;
        t.d1 = FLT_MAX; t.d2 = FLT_MAX; t.i1 = -1; t.i2 = -1;
        #pragma unroll 2
        for (int i = lane; i < NPTS; i += 32) {
            float x = __ldg(&c[3 * i]);
            float y = __ldg(&c[3 * i + 1]);
            float z = __ldg(&c[3 * i + 2]);
            float ddx = qx - x, ddy = qy - y, ddz = qz - z;
            float d = fmaf(ddx, ddx, fmaf(ddy, ddy, ddz * ddz));
            t2_ins(t, d, i);
        }
        Top2 m = warp_merge(t);
        if (lane == 0) g_idx2[side][q] = m.i2;
    }
}

// ---------------- K4: gather features ----------------
// 256 threads per block, 4 rows per block (64 threads = 1 KB row of float4s).
__global__ __launch_bounds__(256)
void gather_kernel(const float* __restrict__ src_feat,
                   const float* __restrict__ tgt_feat,
                   float* __restrict__ out) {
    int row = blockIdx.x * 4 + (threadIdx.x >> 6);   // 0 .. 2*MQ-1
    int col = threadIdx.x & 63;
    int side = (row >= MQ) ? 1 : 0;
    int q = side ? (row - MQ) : row;
    const float* f = side ? tgt_feat : src_feat;
    int idx = g_idx2[side][q];
    const float4* srcp = (const float4*)(f + (size_t)idx * CF);
    float4* dstp = (float4*)(out + (size_t)row * CF);
    dstp[col] = __ldg(&srcp[col]);
}

extern "C" void kernel_launch(void* const* d_in, const int* in_sizes, int n_in,
                              void* d_out, int out_size) {
    const float* src        = (const float*)d_in[0];   // [N, C]
    const float* tgt        = (const float*)d_in[1];   // [N, C]
    const float* src_coords = (const float*)d_in[2];   // [N, 3]
    const float* tgt_coords = (const float*)d_in[3];   // [N, 3]
    const float* src_sc     = (const float*)d_in[4];   // [M, 3]
    const float* tgt_sc     = (const float*)d_in[5];   // [M, 3]
    float* out = (float*)d_out;                        // [2*M, C]

    zero_kernel<<<(2 * G3 + 255) / 256, 256>>>();
    scatter_kernel<<<(2 * NPTS + 255) / 256, 256>>>(src_coords, tgt_coords);
    search1_kernel<<<(2 * MQ * 32 + 255) / 256, 256>>>(src_sc, tgt_sc);
    search2_kernel<<<256, 256>>>(src_coords, tgt_coords, src_sc, tgt_sc);
    gather_kernel<<<2 * MQ / 4, 256>>>(src, tgt, out);
}

// round 5
// speedup vs baseline: 4.6822x; 1.7045x over previous
#include <cuda_runtime.h>
#include <cuda_bf16.h>
#include <cstdint>
#include <cfloat>

// Problem constants
#define NPTS 32768   // candidate points per side
#define MQ   8192    // query (shortcut) points per side
#define CF   256     // feature channels

// Grid constants
#define G     64
#define G3    (G * G * G)          // 262144 cells per side
#define HCELL 0.125f
#define INVH  8.0f
#define ORI   (-4.0f)
#define CAP   16                   // points per bin
#define OVMAX 4096                 // overflow list capacity per side
#define RBOX  2                    // phase-1 box radius (5x5x5 = 125 cells)

// ---------------- scratch ----------------
__device__ int    g_cnt[2 * G3];                 // per-cell counts (2 MB)
__device__ float4 g_bin[2 * G3 * CAP];           // binned points (134 MB)
__device__ int    g_ovn[2];                      // overflow counts
__device__ float4 g_ov[2][OVMAX];                // overflow points
__device__ int    g_idx2[2][MQ];                 // 2nd-NN index per query
__device__ int    g_failn;                       // unresolved query count
__device__ int    g_fail[2 * MQ];                // unresolved (side<<16 | q)
__device__ float  g_faild2[2 * MQ];              // phase-1 d2 upper bound

// ---------------- helpers ----------------
__device__ __forceinline__ int cell_of(float v) {
    int c = (int)floorf((v - ORI) * INVH);
    return min(max(c, 0), G - 1);
}

struct Top2 {
    float d1, d2;
    int   i1, i2;
};

__device__ __forceinline__ void t2_ins(Top2& t, float d, int j) {
    bool a = d < t.d1;
    bool b = d < t.d2;
    t.i2 = a ? t.i1 : (b ? j : t.i2);
    t.d2 = a ? t.d1 : (b ? d : t.d2);
    t.i1 = a ? j : t.i1;
    t.d1 = a ? d : t.d1;
}

__device__ __forceinline__ Top2 warp_merge(Top2 t) {
    #pragma unroll
    for (int off = 16; off; off >>= 1) {
        float od1 = __shfl_xor_sync(0xffffffffu, t.d1, off);
        int   oi1 = __shfl_xor_sync(0xffffffffu, t.i1, off);
        float od2 = __shfl_xor_sync(0xffffffffu, t.d2, off);
        int   oi2 = __shfl_xor_sync(0xffffffffu, t.i2, off);
        t2_ins(t, od1, oi1);
        t2_ins(t, od2, oi2);
    }
    return t;
}

// ---------------- K0: zero counts ----------------
__global__ void zero_kernel() {
    int gid = blockIdx.x * blockDim.x + threadIdx.x;
    if (gid < 2 * G3) g_cnt[gid] = 0;
    if (gid < 2) g_ovn[gid] = 0;
    if (gid == 0) g_failn = 0;
}

// ---------------- K1: scatter points into bins ----------------
__global__ void scatter_kernel(const float* __restrict__ src_coords,
                               const float* __restrict__ tgt_coords) {
    int u = blockIdx.x * blockDim.x + threadIdx.x;
    if (u >= 2 * NPTS) return;
    int side = u >> 15;
    int i = u & (NPTS - 1);
    const float* c = side ? tgt_coords : src_coords;
    float x = c[3 * i], y = c[3 * i + 1], z = c[3 * i + 2];
    int cell = side * G3 + (cell_of(z) * G + cell_of(y)) * G + cell_of(x);
    float4 p = make_float4(x, y, z, __int_as_float(i));
    int slot = atomicAdd(&g_cnt[cell], 1);
    if (slot < CAP) {
        g_bin[cell * CAP + slot] = p;
    } else {
        int o = atomicAdd(&g_ovn[side], 1);
        if (o < OVMAX) g_ov[side][o] = p;
    }
}

// ---------------- K2: phase-1 warp-per-query, fixed r=2 box ----------------
__global__ __launch_bounds__(256)
void search1_kernel(const float* __restrict__ src_sc,
                    const float* __restrict__ tgt_sc) {
    int wid = (blockIdx.x * blockDim.x + threadIdx.x) >> 5;
    int lane = threadIdx.x & 31;
    if (wid >= 2 * MQ) return;
    int side = wid >> 13;
    int q = wid & (MQ - 1);
    const float* sc = side ? tgt_sc : src_sc;
    float qx = sc[3 * q], qy = sc[3 * q + 1], qz = sc[3 * q + 2];
    int cx = cell_of(qx), cy = cell_of(qy), cz = cell_of(qz);
    int sbase = side * G3;

    Top2 t;
    t.d1 = FLT_MAX; t.d2 = FLT_MAX; t.i1 = -1; t.i2 = -1;

    const int S = 2 * RBOX + 1;            // 5
    const int TOT = S * S * S;             // 125
    for (int c = lane; c < TOT; c += 32) {
        int dz = c / (S * S);
        int rem = c - dz * (S * S);
        int dy = rem / S;
        int dx = rem - dy * S;
        int x = cx + dx - RBOX, y = cy + dy - RBOX, z = cz + dz - RBOX;
        if ((unsigned)x >= G || (unsigned)y >= G || (unsigned)z >= G) continue;
        int cell = sbase + (z * G + y) * G + x;
        int n = min(g_cnt[cell], CAP);
        int base = cell * CAP;
        for (int k = 0; k < n; k++) {
            float4 p = g_bin[base + k];
            float ddx = qx - p.x, ddy = qy - p.y, ddz = qz - p.z;
            float d = fmaf(ddx, ddx, fmaf(ddy, ddy, ddz * ddz));
            t2_ins(t, d, __float_as_int(p.w));
        }
    }
    // overflow points (never duplicated in bins)
    int ovn = min(g_ovn[side], OVMAX);
    for (int o = lane; o < ovn; o += 32) {
        float4 p = g_ov[side][o];
        float ddx = qx - p.x, ddy = qy - p.y, ddz = qz - p.z;
        float d = fmaf(ddx, ddx, fmaf(ddy, ddy, ddz * ddz));
        t2_ins(t, d, __float_as_int(p.w));
    }

    Top2 m = warp_merge(t);
    const float bnd2 = (RBOX * HCELL) * (RBOX * HCELL);   // 0.0625
    if (m.d2 <= bnd2) {
        if (lane == 0) g_idx2[side][q] = m.i2;
    } else {
        if (lane == 0) {
            int o = atomicAdd(&g_failn, 1);
            g_fail[o] = (side << 16) | q;
            g_faild2[o] = m.d2;       // valid upper bound when finite
        }
    }
}

// ---------------- K3: phase-2 block-per-item grid search ----------------
// One 256-thread block per failed query. If phase-1 found a finite d2, a
// single box scan of radius r0 = ceil(sqrt(d2)*INVH) is provably sufficient.
// Otherwise escalate geometrically with the ring certificate.
__global__ __launch_bounds__(256)
void search2_kernel(const float* __restrict__ src_sc,
                    const float* __restrict__ tgt_sc) {
    __shared__ Top2 part[8];
    __shared__ Top2 res;
    int tid = threadIdx.x;
    int warp = tid >> 5;
    int lane = tid & 31;
    int nf = g_failn;

    for (int item = blockIdx.x; item < nf; item += gridDim.x) {
        int packed = g_fail[item];
        float d2cap = g_faild2[item];
        int side = packed >> 16;
        int q = packed & 0xffff;
        const float* sc = side ? tgt_sc : src_sc;
        float qx = sc[3 * q], qy = sc[3 * q + 1], qz = sc[3 * q + 2];
        int cx = cell_of(qx), cy = cell_of(qy), cz = cell_of(qz);
        int sbase = side * G3;
        int ovn = min(g_ovn[side], OVMAX);

        bool have_cap = (d2cap < FLT_MAX);
        int r = have_cap ? min((int)ceilf(sqrtf(d2cap) * INVH), G) : 8;

        for (;;) {
            Top2 t;
            t.d1 = FLT_MAX; t.d2 = FLT_MAX; t.i1 = -1; t.i2 = -1;

            int zlo = max(cz - r, 0), zhi = min(cz + r, G - 1);
            int ylo = max(cy - r, 0), yhi = min(cy + r, G - 1);
            int xlo = max(cx - r, 0), xhi = min(cx + r, G - 1);
            int nx = xhi - xlo + 1, ny = yhi - ylo + 1, nz = zhi - zlo + 1;
            int tot = nx * ny * nz;

            for (int c = tid; c < tot; c += 256) {
                int z = c / (nx * ny);
                int rem = c - z * (nx * ny);
                int y = rem / nx;
                int x = rem - y * nx;
                int cell = sbase + ((z + zlo) * G + (y + ylo)) * G + (x + xlo);
                int n = min(g_cnt[cell], CAP);
                int base = cell * CAP;
                for (int k = 0; k < n; k++) {
                    float4 p = g_bin[base + k];
                    float ddx = qx - p.x, ddy = qy - p.y, ddz = qz - p.z;
                    float d = fmaf(ddx, ddx, fmaf(ddy, ddy, ddz * ddz));
                    t2_ins(t, d, __float_as_int(p.w));
                }
            }
            for (int o = tid; o < ovn; o += 256) {
                float4 p = g_ov[side][o];
                float ddx = qx - p.x, ddy = qy - p.y, ddz = qz - p.z;
                float d = fmaf(ddx, ddx, fmaf(ddy, ddy, ddz * ddz));
                t2_ins(t, d, __float_as_int(p.w));
            }

            Top2 w = warp_merge(t);
            if (lane == 0) part[warp] = w;
            __syncthreads();
            if (tid == 0) {
                Top2 m = part[0];
                #pragma unroll
                for (int s = 1; s < 8; s++) {
                    t2_ins(m, part[s].d1, part[s].i1);
                    t2_ins(m, part[s].d2, part[s].i2);
                }
                res = m;
            }
            __syncthreads();
            Top2 m = res;
            __syncthreads();

            if (have_cap || r >= G) {           // single scan was sufficient
                if (tid == 0) g_idx2[side][q] = m.i2;
                break;
            }
            float bnd = (float)r * HCELL;
            if (bnd * bnd >= m.d2) {
                if (tid == 0) g_idx2[side][q] = m.i2;
                break;
            }
            r = min(r * 2, G);                  // rare: escalate
        }
    }
}

// ---------------- K4: gather features ----------------
// 256 threads per block, 4 rows per block (64 threads = 1 KB row of float4s).
__global__ __launch_bounds__(256)
void gather_kernel(const float* __restrict__ src_feat,
                   const float* __restrict__ tgt_feat,
                   float* __restrict__ out) {
    int row = blockIdx.x * 4 + (threadIdx.x >> 6);   // 0 .. 2*MQ-1
    int col = threadIdx.x & 63;
    int side = (row >= MQ) ? 1 : 0;
    int q = side ? (row - MQ) : row;
    const float* f = side ? tgt_feat : src_feat;
    int idx = g_idx2[side][q];
    const float4* srcp = (const float4*)(f + (size_t)idx * CF);
    float4* dstp = (float4*)(out + (size_t)row * CF);
    dstp[col] = __ldg(&srcp[col]);
}

extern "C" void kernel_launch(void* const* d_in, const int* in_sizes, int n_in,
                              void* d_out, int out_size) {
    const float* src        = (const float*)d_in[0];   // [N, C]
    const float* tgt        = (const float*)d_in[1];   // [N, C]
    const float* src_coords = (const float*)d_in[2];   // [N, 3]
    const float* tgt_coords = (const float*)d_in[3];   // [N, 3]
    const float* src_sc     = (const float*)d_in[4];   // [M, 3]
    const float* tgt_sc     = (const float*)d_in[5];   // [M, 3]
    float* out = (float*)d_out;                        // [2*M, C]

    zero_kernel<<<(2 * G3 + 255) / 256, 256>>>();
    scatter_kernel<<<(2 * NPTS + 255) / 256, 256>>>(src_coords, tgt_coords);
    search1_kernel<<<(2 * MQ * 32 + 255) / 256, 256>>>(src_sc, tgt_sc);
    search2_kernel<<<2048, 256>>>(src_sc, tgt_sc);
    gather_kernel<<<2 * MQ / 4, 256>>>(src, tgt, out);
}

// round 6
// speedup vs baseline: 7.1232x; 1.5213x over previous
#include <cuda_runtime.h>
#include <cuda_bf16.h>
#include <cstdint>
#include <cfloat>

// Problem constants
#define NPTS 32768   // candidate points per side
#define MQ   8192    // query (shortcut) points per side
#define CF   256     // feature channels

// Grid constants
#define G     64
#define G3    (G * G * G)          // 262144 cells per side
#define HCELL 0.125f
#define INVH  8.0f
#define ORI   (-4.0f)
#define CAP   16                   // points per bin
#define OVMAX 4096                 // overflow list capacity per side
#define RBOX  2                    // phase-1 box radius (5x5x5 = 125 cells)

// ---------------- scratch ----------------
__device__ int    g_cnt[2 * G3];                 // per-cell counts (2 MB)
__device__ float4 g_bin[2 * G3 * CAP];           // binned points (134 MB)
__device__ int    g_ovn[2];                      // overflow counts
__device__ float4 g_ov[2][OVMAX];                // overflow points
__device__ float4 g_pts4[2][NPTS];               // packed points for phase-2
__device__ int    g_idx2[2][MQ];                 // 2nd-NN index per query
__device__ int    g_failn;                       // unresolved query count
__device__ int    g_fail[2 * MQ];                // unresolved (side<<16 | q)

// ---------------- helpers ----------------
__device__ __forceinline__ int cell_of(float v) {
    int c = (int)floorf((v - ORI) * INVH);
    return min(max(c, 0), G - 1);
}

struct Top2 {
    float d1, d2;
    int   i1, i2;
};

__device__ __forceinline__ void t2_ins(Top2& t, float d, int j) {
    bool a = d < t.d1;
    bool b = d < t.d2;
    t.i2 = a ? t.i1 : (b ? j : t.i2);
    t.d2 = a ? t.d1 : (b ? d : t.d2);
    t.i1 = a ? j : t.i1;
    t.d1 = a ? d : t.d1;
}

__device__ __forceinline__ Top2 warp_merge(Top2 t) {
    #pragma unroll
    for (int off = 16; off; off >>= 1) {
        float od1 = __shfl_xor_sync(0xffffffffu, t.d1, off);
        int   oi1 = __shfl_xor_sync(0xffffffffu, t.i1, off);
        float od2 = __shfl_xor_sync(0xffffffffu, t.d2, off);
        int   oi2 = __shfl_xor_sync(0xffffffffu, t.i2, off);
        t2_ins(t, od1, oi1);
        t2_ins(t, od2, oi2);
    }
    return t;
}

// merge b into a, preferring lower index on exact ties via insertion order:
// insert b's elements after a's (strict <, so a's win ties) — but for
// cross-lane partials the index sets are disjoint ranges in scan order, and
// exact fp ties across distinct random points don't occur in practice.
__device__ __forceinline__ void t2_merge(Top2& a, const Top2& b) {
    t2_ins(a, b.d1, b.i1);
    t2_ins(a, b.d2, b.i2);
}

// ---------------- K0: zero counts ----------------
__global__ void zero_kernel() {
    int gid = blockIdx.x * blockDim.x + threadIdx.x;
    if (gid < 2 * G3) g_cnt[gid] = 0;
    if (gid < 2) g_ovn[gid] = 0;
    if (gid == 0) g_failn = 0;
}

// ---------------- K1: scatter points into bins + packed array ----------------
__global__ void scatter_kernel(const float* __restrict__ src_coords,
                               const float* __restrict__ tgt_coords) {
    int u = blockIdx.x * blockDim.x + threadIdx.x;
    if (u >= 2 * NPTS) return;
    int side = u >> 15;
    int i = u & (NPTS - 1);
    const float* c = side ? tgt_coords : src_coords;
    float x = c[3 * i], y = c[3 * i + 1], z = c[3 * i + 2];
    int cell = side * G3 + (cell_of(z) * G + cell_of(y)) * G + cell_of(x);
    float4 p = make_float4(x, y, z, __int_as_float(i));
    g_pts4[side][i] = p;
    int slot = atomicAdd(&g_cnt[cell], 1);
    if (slot < CAP) {
        g_bin[cell * CAP + slot] = p;
    } else {
        int o = atomicAdd(&g_ovn[side], 1);
        if (o < OVMAX) g_ov[side][o] = p;
    }
}

// ---------------- K2: phase-1 warp-per-query, fixed r=2 box ----------------
__global__ __launch_bounds__(256)
void search1_kernel(const float* __restrict__ src_sc,
                    const float* __restrict__ tgt_sc) {
    int wid = (blockIdx.x * blockDim.x + threadIdx.x) >> 5;
    int lane = threadIdx.x & 31;
    if (wid >= 2 * MQ) return;
    int side = wid >> 13;
    int q = wid & (MQ - 1);
    const float* sc = side ? tgt_sc : src_sc;
    float qx = sc[3 * q], qy = sc[3 * q + 1], qz = sc[3 * q + 2];
    int cx = cell_of(qx), cy = cell_of(qy), cz = cell_of(qz);
    int sbase = side * G3;

    Top2 t;
    t.d1 = FLT_MAX; t.d2 = FLT_MAX; t.i1 = -1; t.i2 = -1;

    const int S = 2 * RBOX + 1;            // 5
    const int TOT = S * S * S;             // 125
    for (int c = lane; c < TOT; c += 32) {
        int dz = c / (S * S);
        int rem = c - dz * (S * S);
        int dy = rem / S;
        int dx = rem - dy * S;
        int x = cx + dx - RBOX, y = cy + dy - RBOX, z = cz + dz - RBOX;
        if ((unsigned)x >= G || (unsigned)y >= G || (unsigned)z >= G) continue;
        int cell = sbase + (z * G + y) * G + x;
        int n = min(g_cnt[cell], CAP);
        int base = cell * CAP;
        for (int k = 0; k < n; k++) {
            float4 p = g_bin[base + k];
            float ddx = qx - p.x, ddy = qy - p.y, ddz = qz - p.z;
            float d = fmaf(ddx, ddx, fmaf(ddy, ddy, ddz * ddz));
            t2_ins(t, d, __float_as_int(p.w));
        }
    }
    // overflow points (never duplicated in bins)
    int ovn = min(g_ovn[side], OVMAX);
    for (int o = lane; o < ovn; o += 32) {
        float4 p = g_ov[side][o];
        float ddx = qx - p.x, ddy = qy - p.y, ddz = qz - p.z;
        float d = fmaf(ddx, ddx, fmaf(ddy, ddy, ddz * ddz));
        t2_ins(t, d, __float_as_int(p.w));
    }

    Top2 m = warp_merge(t);
    const float bnd2 = (RBOX * HCELL) * (RBOX * HCELL);   // 0.0625
    if (m.d2 <= bnd2) {
        if (lane == 0) g_idx2[side][q] = m.i2;
    } else {
        if (lane == 0) {
            int o = atomicAdd(&g_failn, 1);
            g_fail[o] = (side << 16) | q;
        }
    }
}

// ---------------- K3: phase-2 block-per-item exact brute force ----------------
// 256 threads scan all NPTS packed points: 32 steps x 4 independent
// accumulators (stride 256 within step) -> issue-limited, uniform, bounded.
__global__ __launch_bounds__(256)
void search2_kernel(const float* __restrict__ src_sc,
                    const float* __restrict__ tgt_sc) {
    __shared__ Top2 part[8];
    int tid = threadIdx.x;
    int warp = tid >> 5;
    int lane = tid & 31;
    int nf = g_failn;

    for (int item = blockIdx.x; item < nf; item += gridDim.x) {
        int packed = g_fail[item];
        int side = packed >> 16;
        int q = packed & 0xffff;
        const float* sc = side ? tgt_sc : src_sc;
        float qx = sc[3 * q], qy = sc[3 * q + 1], qz = sc[3 * q + 2];
        const float4* pts = g_pts4[side];

        Top2 t0, t1, t2, t3;
        t0.d1 = FLT_MAX; t0.d2 = FLT_MAX; t0.i1 = -1; t0.i2 = -1;
        t1 = t0; t2 = t0; t3 = t0;

        #pragma unroll 4
        for (int base = 0; base < NPTS; base += 1024) {
            int i0 = base + tid;
            float4 p0 = __ldg(&pts[i0]);
            float4 p1 = __ldg(&pts[i0 + 256]);
            float4 p2 = __ldg(&pts[i0 + 512]);
            float4 p3 = __ldg(&pts[i0 + 768]);
            float dx0 = qx - p0.x, dy0 = qy - p0.y, dz0 = qz - p0.z;
            float dx1 = qx - p1.x, dy1 = qy - p1.y, dz1 = qz - p1.z;
            float dx2 = qx - p2.x, dy2 = qy - p2.y, dz2 = qz - p2.z;
            float dx3 = qx - p3.x, dy3 = qy - p3.y, dz3 = qz - p3.z;
            float d0 = fmaf(dx0, dx0, fmaf(dy0, dy0, dz0 * dz0));
            float d1 = fmaf(dx1, dx1, fmaf(dy1, dy1, dz1 * dz1));
            float d2 = fmaf(dx2, dx2, fmaf(dy2, dy2, dz2 * dz2));
            float d3 = fmaf(dx3, dx3, fmaf(dy3, dy3, dz3 * dz3));
            t2_ins(t0, d0, i0);
            t2_ins(t1, d1, i0 + 256);
            t2_ins(t2, d2, i0 + 512);
            t2_ins(t3, d3, i0 + 768);
        }
        t2_merge(t0, t1);
        t2_merge(t2, t3);
        t2_merge(t0, t2);

        Top2 w = warp_merge(t0);
        if (lane == 0) part[warp] = w;
        __syncthreads();
        if (tid == 0) {
            Top2 m = part[0];
            #pragma unroll
            for (int s = 1; s < 8; s++) t2_merge(m, part[s]);
            g_idx2[side][q] = m.i2;
        }
        __syncthreads();
    }
}

// ---------------- K4: gather features ----------------
// 256 threads per block, 4 rows per block (64 threads = 1 KB row of float4s).
__global__ __launch_bounds__(256)
void gather_kernel(const float* __restrict__ src_feat,
                   const float* __restrict__ tgt_feat,
                   float* __restrict__ out) {
    int row = blockIdx.x * 4 + (threadIdx.x >> 6);   // 0 .. 2*MQ-1
    int col = threadIdx.x & 63;
    int side = (row >= MQ) ? 1 : 0;
    int q = side ? (row - MQ) : row;
    const float* f = side ? tgt_feat : src_feat;
    int idx = g_idx2[side][q];
    const float4* srcp = (const float4*)(f + (size_t)idx * CF);
    float4* dstp = (float4*)(out + (size_t)row * CF);
    dstp[col] = __ldg(&srcp[col]);
}

extern "C" void kernel_launch(void* const* d_in, const int* in_sizes, int n_in,
                              void* d_out, int out_size) {
    const float* src        = (const float*)d_in[0];   // [N, C]
    const float* tgt        = (const float*)d_in[1];   // [N, C]
    const float* src_coords = (const float*)d_in[2];   // [N, 3]
    const float* tgt_coords = (const float*)d_in[3];   // [N, 3]
    const float* src_sc     = (const float*)d_in[4];   // [M, 3]
    const float* tgt_sc     = (const float*)d_in[5];   // [M, 3]
    float* out = (float*)d_out;                        // [2*M, C]

    zero_kernel<<<(2 * G3 + 255) / 256, 256>>>();
    scatter_kernel<<<(2 * NPTS + 255) / 256, 256>>>(src_coords, tgt_coords);
    search1_kernel<<<(2 * MQ * 32 + 255) / 256, 256>>>(src_sc, tgt_sc);
    search2_kernel<<<2048, 256>>>(src_sc, tgt_sc);
    gather_kernel<<<2 * MQ / 4, 256>>>(src, tgt, out);
}